// round 12
// baseline (speedup 1.0000x reference)
#include <cuda_runtime.h>
#include <cuda_bf16.h>
#include <cstdint>

// BatchRankingLoss: G=511 groups of d=256 decoys.
// loss = sum_{g,i,j} w_ij * max(0, 1 + y_ij*(o_i - o_j)) / (G*d*(d-1))
//   y_ij = -1 if (t_i - t_j) < 0 else +1 ;  w_ij = |t_i - t_j| > 0.1
//
// Symmetry: term(i,j)==term(j,i) -> sum = 2 * sum over unordered pairs.
// Per row i: m=1..127 full weight, m=128 half weight (distance-128 pairs are
// generated by both endpoints).
//
// CTA = 256 threads = ONE group. u=tid&63 -> 4-row block (rows 4u..4u+3 in
// regs); h=tid>>6 -> compile-time 4-way column split (s = col offset from
// block base; row k sees m = s-k):
//   h=0: prologue s=1..3 + pairs s=4..33   (15 packed pairs)
//   h=1: pairs s=34..65  (16)
//   h=2: pairs s=66..97  (16)
//   h=3: pairs s=98..127 (15) + epilogue s=128..131 (m=128 -> half weight)
//
// R8/R11 lesson: fully-unrolled straight-line slices (~12KB code) cap issue
// ~50% via cold I$ streaming (issue FELL 50->44.5% as occ rose 20->46%).
// R9 lesson: runtime bounds/pointers cost ~1.1M extra warp-instrs.
// This version: LOOPED slices (partial unroll, constant trip count) so the
// ~0.6KB body stays hot in L0, with a SINGLE combined smem array
// (neg[0..383] = -t, neg[384..767] = -o) so both packed LDS.64 operands are
// immediate offsets off ONE base register -> loop overhead ~1 IADD + branch
// per 4-5 pairs. Arrays padded to 384 rows (first 128 duplicated): no wrap.
//
// Fused reduction: group sums -> scratch; last CTA (ticket) writes d_out and
// resets the ticket -> graph-replay deterministic.

#define D      256
#define PAD2   384      // per-array stride (rows) inside combined smem
#define THRESH 0.1f

__device__ float    g_group_sums[4096];
__device__ unsigned g_ticket;   // zero-init; reset by last CTA each call

__device__ __forceinline__ uint64_t f32x2_add(uint64_t a, uint64_t b)
{
    uint64_t r;
    asm("add.rn.f32x2 %0, %1, %2;" : "=l"(r) : "l"(a), "l"(b));
    return r;
}
__device__ __forceinline__ uint64_t pack2(float lo, float hi)
{
    uint64_t r;
    asm("mov.b64 %0, {%1, %2};" : "=l"(r) : "f"(lo), "f"(hi));
    return r;
}
__device__ __forceinline__ void unpack2(uint64_t v, float& lo, float& hi)
{
    asm("mov.b64 {%0, %1}, %2;" : "=f"(lo), "=f"(hi) : "l"(v));
}

__device__ __forceinline__ void acc_half(float& acc, float dt, float dd)
{
    // y*do via sign-bit xor (y=-1 iff dt<0; dt==+-0 is weighted out)
    const uint32_t s =
        __float_as_uint(dd) ^ (__float_as_uint(dt) & 0x80000000u);
    const float q = fmaxf(0.0f, 1.0f + __uint_as_float(s));
    if (fabsf(dt) > THRESH) acc += q;          // predicated FADD
}

// scalar term; base[s] = -t[row r+s], base[PAD2+s] = -o[row r+s]
__device__ __forceinline__ void acc_neg(float& acc, float oi, float ti,
                                        const float* base, int s)
{
    acc_half(acc, ti + base[s], oi + base[PAD2 + s]);
}

// One slice: NP packed column-pairs starting at compile-time S0, as a
// partially-unrolled loop (body stays resident in L0 I$).
template <int S0, int NP, int UNR>
__device__ __forceinline__ void do_slice(const float* base,
                                         const uint64_t* oi2, const uint64_t* ti2,
                                         float* accA, float* accB)
{
#pragma unroll (UNR)
    for (int p = 0; p < NP; ++p) {
        const uint64_t ntj2 =
            *reinterpret_cast<const uint64_t*>(base + S0 + 2 * p);          // LDS.64
        const uint64_t noj2 =
            *reinterpret_cast<const uint64_t*>(base + PAD2 + S0 + 2 * p);   // LDS.64
#pragma unroll
        for (int k = 0; k < 4; ++k) {
            float dtl, dth, ddl, ddh;
            unpack2(f32x2_add(ti2[k], ntj2), dtl, dth);
            unpack2(f32x2_add(oi2[k], noj2), ddl, ddh);
            acc_half(accA[k], dtl, ddl);
            acc_half(accB[k], dth, ddh);
        }
    }
}

__global__ __launch_bounds__(256) void ranking_loss_kernel(
    const float* __restrict__ o_in,   // [B,1] -> [B]
    const float* __restrict__ t_in,   // [B]
    float* __restrict__ out,
    int G)
{
    __shared__ __align__(16) float neg[2 * PAD2];   // [-t | -o]
    __shared__ float wsum[8];
    __shared__ bool  is_last;

    const int tid = threadIdx.x;
    const int u   = tid & 63;          // 4-row block index
    const int h   = tid >> 6;          // column slice (warp-uniform)
    const int g   = blockIdx.x;
    const int r   = 4 * u;

    const float4 o4 = reinterpret_cast<const float4*>(o_in)[g * 64 + u];
    const float4 t4 = reinterpret_cast<const float4*>(t_in)[g * 64 + u];

    if (h == 0) {                      // one writer per 4-row block
        neg[r + 0] = -t4.x; neg[r + 1] = -t4.y;
        neg[r + 2] = -t4.z; neg[r + 3] = -t4.w;
        neg[PAD2 + r + 0] = -o4.x; neg[PAD2 + r + 1] = -o4.y;
        neg[PAD2 + r + 2] = -o4.z; neg[PAD2 + r + 3] = -o4.w;
        if (r < 128) {                 // duplicate first 128 rows -> no wrap
            neg[D + r + 0] = -t4.x; neg[D + r + 1] = -t4.y;
            neg[D + r + 2] = -t4.z; neg[D + r + 3] = -t4.w;
            neg[PAD2 + D + r + 0] = -o4.x; neg[PAD2 + D + r + 1] = -o4.y;
            neg[PAD2 + D + r + 2] = -o4.z; neg[PAD2 + D + r + 3] = -o4.w;
        }
    }
    __syncthreads();

    const float* base = neg + r;       // base[s] = -t[r+s]; base[PAD2+s] = -o[r+s]

    const float oi[4] = {o4.x, o4.y, o4.z, o4.w};
    const float ti[4] = {t4.x, t4.y, t4.z, t4.w};
    uint64_t oi2[4], ti2[4];
#pragma unroll
    for (int k = 0; k < 4; ++k) {
        oi2[k] = pack2(oi[k], oi[k]);
        ti2[k] = pack2(ti[k], ti[k]);
    }

    float accA[4] = {0.f, 0.f, 0.f, 0.f};
    float accB[4] = {0.f, 0.f, 0.f, 0.f};
    float ah = 0.f;                    // m=128 half-weight accumulator

    switch (h) {
    case 0:
        do_slice<4, 15, 5>(base, oi2, ti2, accA, accB);
        // prologue: s=1..3 (only rows with m = s-k >= 1)
        acc_neg(accA[0], oi[0], ti[0], base, 1);
        acc_neg(accA[0], oi[0], ti[0], base, 2);
        acc_neg(accA[1], oi[1], ti[1], base, 2);
        acc_neg(accA[0], oi[0], ti[0], base, 3);
        acc_neg(accA[1], oi[1], ti[1], base, 3);
        acc_neg(accA[2], oi[2], ti[2], base, 3);
        break;
    case 1:
        do_slice<34, 16, 4>(base, oi2, ti2, accA, accB);
        break;
    case 2:
        do_slice<66, 16, 4>(base, oi2, ti2, accA, accB);
        break;
    default:
        do_slice<98, 15, 5>(base, oi2, ti2, accA, accB);
        // epilogue: s=128..131 ; m==128 terms -> half-weight acc
        acc_neg(ah,      oi[0], ti[0], base, 128);   // m=128
        acc_neg(accA[1], oi[1], ti[1], base, 128);   // m=127
        acc_neg(accA[2], oi[2], ti[2], base, 128);   // m=126
        acc_neg(accA[3], oi[3], ti[3], base, 128);   // m=125
        acc_neg(ah,      oi[1], ti[1], base, 129);   // m=128
        acc_neg(accA[2], oi[2], ti[2], base, 129);
        acc_neg(accA[3], oi[3], ti[3], base, 129);
        acc_neg(ah,      oi[2], ti[2], base, 130);   // m=128
        acc_neg(accA[3], oi[3], ti[3], base, 130);
        acc_neg(ah,      oi[3], ti[3], base, 131);   // m=128
        break;
    }

    float acc = ((accA[0] + accB[0]) + (accA[1] + accB[1]))
              + ((accA[2] + accB[2]) + (accA[3] + accB[3]))
              + 0.5f * ah;

    // CTA reduce (8 warps)
#pragma unroll
    for (int off = 16; off > 0; off >>= 1)
        acc += __shfl_xor_sync(0xffffffffu, acc, off);
    if ((tid & 31) == 0) wsum[tid >> 5] = acc;
    __syncthreads();

    if (tid == 0) {
        float s = 0.f;
#pragma unroll
        for (int w = 0; w < 8; ++w) s += wsum[w];
        g_group_sums[g] = s;
        __threadfence();
        unsigned old = atomicAdd(&g_ticket, 1u);
        is_last = (old == (unsigned)(G - 1));
    }
    __syncthreads();

    if (is_last) {
        __threadfence();                    // acquire other CTAs' sums
        float v = (tid < G) ? g_group_sums[tid] : 0.f;
        if (tid + 256 < G) v += g_group_sums[tid + 256];

#pragma unroll
        for (int off = 16; off > 0; off >>= 1)
            v += __shfl_xor_sync(0xffffffffu, v, off);
        if ((tid & 31) == 0) wsum[tid >> 5] = v;
        __syncthreads();

        if (tid == 0) {
            float s = 0.f;
#pragma unroll
            for (int w = 0; w < 8; ++w) s += wsum[w];
            const float inv_n = 1.0f / ((float)G * (float)D * (float)(D - 1));
            out[0] = 2.0f * s * inv_n;      // x2: unordered -> ordered pairs
            g_ticket = 0;                   // reset for next graph replay
        }
    }
}

extern "C" void kernel_launch(void* const* d_in, const int* in_sizes, int n_in,
                              void* d_out, int out_size)
{
    const float* o = (const float*)d_in[0];  // input  [B,1] f32
    const float* t = (const float*)d_in[1];  // gdt_ts [B]   f32
    float* out = (float*)d_out;

    const int B = in_sizes[1];
    const int K = B / D;            // 512
    const int G = K - 1;            // 511 (reference skips final group)

    ranking_loss_kernel<<<G, 256>>>(o, t, out, G);
}

// round 13
// speedup vs baseline: 1.0030x; 1.0030x over previous
#include <cuda_runtime.h>
#include <cuda_bf16.h>
#include <cstdint>

// BatchRankingLoss: G=511 groups of d=256 decoys.
// loss = sum_{g,i,j} w_ij * max(0, 1 + y_ij*(o_i - o_j)) / (G*d*(d-1))
//   y_ij = -1 if (t_i - t_j) < 0 else +1 ;  w_ij = |t_i - t_j| > 0.1
//
// Symmetry: term(i,j)==term(j,i) -> sum = 2 * sum over unordered pairs.
// Per row i: m=1..127 full weight, m=128 half weight.
//
// Structure = R12 (best issue): CTA = 256 thr = ONE group; u=tid&63 -> 4-row
// block (rows 4u..4u+3 in regs); h=tid>>6 -> compile-time column slice, each
// a partially-unrolled loop (hot in L0 I$); packed f32x2 for dt/dd.
//
// R12 fixes applied this round:
// (a) GUARDED ACC VIA EXPLICIT PTX PREDICATION. ptxas does not if-convert
//     C++ `if{}` short arms (BSSY/BSYNC emitted instead, ~+3 instr/term and
//     divergence stalls) — write setp + @p add.f32 directly.
// (b) BANK-CONFLICT-FREE LDS: lane bases are stride-4 floats, so lanes u and
//     u+8 collide per half-warp phase. Keep TWO copies of the data; copy 1
//     lives at float offset 770 (770 mod 32 == 2), and lanes with (u>>3)&1
//     read copy 1 -> per 16-lane phase banks {4k,4k+1} U {4k+2,4k+3} = all
//     32 banks. Copy select folds into the base pointer once; inner offsets
//     stay immediates.
//
// Per copy: [-t | rows 0..383] at [0,384), [-o] at [384,768); rows padded to
// 384 (first 128 duplicated) so column index r+s (s<=131) never wraps.
//
// Fused reduction: group sums -> scratch; last CTA (ticket) writes d_out and
// resets the ticket -> graph-replay deterministic.

#define D       256
#define PAD2    384           // o-section offset within a copy (floats)
#define CPY     770           // copy stride in floats; 770 % 32 == 2
#define THRESH  0.1f

__device__ float    g_group_sums[4096];
__device__ unsigned g_ticket;   // zero-init; reset by last CTA each call

__device__ __forceinline__ uint64_t f32x2_add(uint64_t a, uint64_t b)
{
    uint64_t r;
    asm("add.rn.f32x2 %0, %1, %2;" : "=l"(r) : "l"(a), "l"(b));
    return r;
}
__device__ __forceinline__ uint64_t pack2(float lo, float hi)
{
    uint64_t r;
    asm("mov.b64 %0, {%1, %2};" : "=l"(r) : "f"(lo), "f"(hi));
    return r;
}
__device__ __forceinline__ void unpack2(uint64_t v, float& lo, float& hi)
{
    asm("mov.b64 {%0, %1}, %2;" : "=f"(lo), "=f"(hi) : "l"(v));
}

__device__ __forceinline__ void acc_half(float& acc, float dt, float dd)
{
    // y*do via sign-bit xor (y=-1 iff dt<0; dt==+-0 is weighted out)
    const uint32_t s =
        __float_as_uint(dd) ^ (__float_as_uint(dt) & 0x80000000u);
    const float q   = fmaxf(0.0f, 1.0f + __uint_as_float(s));
    const float adt = fabsf(dt);
    // Explicit PTX predication: FSETP + @P FADD, no BSSY/BSYNC.
    asm("{ .reg .pred p;\n\t"
        "  setp.gt.f32 p, %1, 0f3DCCCCCD;\n\t"   // |dt| > 0.1f
        "  @p add.f32 %0, %0, %2;\n\t"
        "}"
        : "+f"(acc) : "f"(adt), "f"(q));
}

// scalar term; base[s] = -t[row r+s], base[PAD2+s] = -o[row r+s]
__device__ __forceinline__ void acc_neg(float& acc, float oi, float ti,
                                        const float* base, int s)
{
    acc_half(acc, ti + base[s], oi + base[PAD2 + s]);
}

// One slice: NP packed column-pairs starting at compile-time S0, as a
// partially-unrolled loop (body stays resident in L0 I$).
template <int S0, int NP, int UNR>
__device__ __forceinline__ void do_slice(const float* base,
                                         const uint64_t* oi2, const uint64_t* ti2,
                                         float* accA, float* accB)
{
#pragma unroll (UNR)
    for (int p = 0; p < NP; ++p) {
        const uint64_t ntj2 =
            *reinterpret_cast<const uint64_t*>(base + S0 + 2 * p);          // LDS.64
        const uint64_t noj2 =
            *reinterpret_cast<const uint64_t*>(base + PAD2 + S0 + 2 * p);   // LDS.64
#pragma unroll
        for (int k = 0; k < 4; ++k) {
            float dtl, dth, ddl, ddh;
            unpack2(f32x2_add(ti2[k], ntj2), dtl, dth);
            unpack2(f32x2_add(oi2[k], noj2), ddl, ddh);
            acc_half(accA[k], dtl, ddl);
            acc_half(accB[k], dth, ddh);
        }
    }
}

__global__ __launch_bounds__(256) void ranking_loss_kernel(
    const float* __restrict__ o_in,   // [B,1] -> [B]
    const float* __restrict__ t_in,   // [B]
    float* __restrict__ out,
    int G)
{
    __shared__ __align__(16) float neg[2 * CPY];    // two shifted copies
    __shared__ float wsum[8];
    __shared__ bool  is_last;

    const int tid = threadIdx.x;
    const int u   = tid & 63;          // 4-row block index
    const int h   = tid >> 6;          // column slice (warp-uniform)
    const int g   = blockIdx.x;
    const int r   = 4 * u;

    const float4 o4 = reinterpret_cast<const float4*>(o_in)[g * 64 + u];
    const float4 t4 = reinterpret_cast<const float4*>(t_in)[g * 64 + u];

    if (h == 0) {                      // one writer per 4-row block; fill BOTH copies
#pragma unroll
        for (int c = 0; c < 2; ++c) {
            float* nb = neg + c * CPY;
            nb[r + 0] = -t4.x; nb[r + 1] = -t4.y;
            nb[r + 2] = -t4.z; nb[r + 3] = -t4.w;
            nb[PAD2 + r + 0] = -o4.x; nb[PAD2 + r + 1] = -o4.y;
            nb[PAD2 + r + 2] = -o4.z; nb[PAD2 + r + 3] = -o4.w;
            if (r < 128) {             // duplicate first 128 rows -> no wrap
                nb[D + r + 0] = -t4.x; nb[D + r + 1] = -t4.y;
                nb[D + r + 2] = -t4.z; nb[D + r + 3] = -t4.w;
                nb[PAD2 + D + r + 0] = -o4.x; nb[PAD2 + D + r + 1] = -o4.y;
                nb[PAD2 + D + r + 2] = -o4.z; nb[PAD2 + D + r + 3] = -o4.w;
            }
        }
    }
    __syncthreads();

    // copy select: lanes with (u>>3)&1 read the +2-bank-shifted copy
    const float* base = neg + r + ((u >> 3) & 1) * CPY;

    const float oi[4] = {o4.x, o4.y, o4.z, o4.w};
    const float ti[4] = {t4.x, t4.y, t4.z, t4.w};
    uint64_t oi2[4], ti2[4];
#pragma unroll
    for (int k = 0; k < 4; ++k) {
        oi2[k] = pack2(oi[k], oi[k]);
        ti2[k] = pack2(ti[k], ti[k]);
    }

    float accA[4] = {0.f, 0.f, 0.f, 0.f};
    float accB[4] = {0.f, 0.f, 0.f, 0.f};
    float ah = 0.f;                    // m=128 half-weight accumulator

    switch (h) {
    case 0:
        do_slice<4, 15, 5>(base, oi2, ti2, accA, accB);
        // prologue: s=1..3 (only rows with m = s-k >= 1)
        acc_neg(accA[0], oi[0], ti[0], base, 1);
        acc_neg(accA[0], oi[0], ti[0], base, 2);
        acc_neg(accA[1], oi[1], ti[1], base, 2);
        acc_neg(accA[0], oi[0], ti[0], base, 3);
        acc_neg(accA[1], oi[1], ti[1], base, 3);
        acc_neg(accA[2], oi[2], ti[2], base, 3);
        break;
    case 1:
        do_slice<34, 16, 4>(base, oi2, ti2, accA, accB);
        break;
    case 2:
        do_slice<66, 16, 4>(base, oi2, ti2, accA, accB);
        break;
    default:
        do_slice<98, 15, 5>(base, oi2, ti2, accA, accB);
        // epilogue: s=128..131 ; m==128 terms -> half-weight acc
        acc_neg(ah,      oi[0], ti[0], base, 128);   // m=128
        acc_neg(accA[1], oi[1], ti[1], base, 128);   // m=127
        acc_neg(accA[2], oi[2], ti[2], base, 128);   // m=126
        acc_neg(accA[3], oi[3], ti[3], base, 128);   // m=125
        acc_neg(ah,      oi[1], ti[1], base, 129);   // m=128
        acc_neg(accA[2], oi[2], ti[2], base, 129);
        acc_neg(accA[3], oi[3], ti[3], base, 129);
        acc_neg(ah,      oi[2], ti[2], base, 130);   // m=128
        acc_neg(accA[3], oi[3], ti[3], base, 130);
        acc_neg(ah,      oi[3], ti[3], base, 131);   // m=128
        break;
    }

    float acc = ((accA[0] + accB[0]) + (accA[1] + accB[1]))
              + ((accA[2] + accB[2]) + (accA[3] + accB[3]))
              + 0.5f * ah;

    // CTA reduce (8 warps)
#pragma unroll
    for (int off = 16; off > 0; off >>= 1)
        acc += __shfl_xor_sync(0xffffffffu, acc, off);
    if ((tid & 31) == 0) wsum[tid >> 5] = acc;
    __syncthreads();

    if (tid == 0) {
        float s = 0.f;
#pragma unroll
        for (int w = 0; w < 8; ++w) s += wsum[w];
        g_group_sums[g] = s;
        __threadfence();
        unsigned old = atomicAdd(&g_ticket, 1u);
        is_last = (old == (unsigned)(G - 1));
    }
    __syncthreads();

    if (is_last) {
        __threadfence();                    // acquire other CTAs' sums
        float v = (tid < G) ? g_group_sums[tid] : 0.f;
        if (tid + 256 < G) v += g_group_sums[tid + 256];

#pragma unroll
        for (int off = 16; off > 0; off >>= 1)
            v += __shfl_xor_sync(0xffffffffu, v, off);
        if ((tid & 31) == 0) wsum[tid >> 5] = v;
        __syncthreads();

        if (tid == 0) {
            float s = 0.f;
#pragma unroll
            for (int w = 0; w < 8; ++w) s += wsum[w];
            const float inv_n = 1.0f / ((float)G * (float)D * (float)(D - 1));
            out[0] = 2.0f * s * inv_n;      // x2: unordered -> ordered pairs
            g_ticket = 0;                   // reset for next graph replay
        }
    }
}

extern "C" void kernel_launch(void* const* d_in, const int* in_sizes, int n_in,
                              void* d_out, int out_size)
{
    const float* o = (const float*)d_in[0];  // input  [B,1] f32
    const float* t = (const float*)d_in[1];  // gdt_ts [B]   f32
    float* out = (float*)d_out;

    const int B = in_sizes[1];
    const int K = B / D;            // 512
    const int G = K - 1;            // 511 (reference skips final group)

    ranking_loss_kernel<<<G, 256>>>(o, t, out, G);
}